// round 8
// baseline (speedup 1.0000x reference)
#include <cuda_runtime.h>
#include <cuda_bf16.h>
#include <cstdint>

#define NN   10000
#define EE   320000
#define RR   460
#define BB   30
#define DD   200
#define KTOT 6200
#define KPAD 6208            // multiple of 64
#define MPAD 10112           // 79 * 128
#define NPAD 224
#define NCHTOT 194           // KPAD / 32
#define NKSL  16
#define NMT   79
#define NUNITS (NMT * NKSL)

// ---- device scratch (zero-initialized; pads never written -> stay 0) ----
__device__ __align__(256) __nv_bfloat16 g_Ah[(size_t)MPAD * KPAD];
__device__ __align__(256) __nv_bfloat16 g_Al[(size_t)MPAD * KPAD];
__device__ __align__(256) __nv_bfloat16 g_Bh[(size_t)NPAD * KPAD];
__device__ __align__(256) __nv_bfloat16 g_Bl[(size_t)NPAD * KPAD];
__device__ __align__(256) __nv_bfloat16 g_Xh[(size_t)NN * DD];
__device__ __align__(256) __nv_bfloat16 g_Xl[(size_t)NN * DD];
__device__ __align__(256) __nv_bfloat16 g_Crh[(RR + 1) * 32];   // row RR = zeros (pad)
__device__ __align__(256) __nv_bfloat16 g_Crl[(RR + 1) * 32];
__device__ int g_deg[NN];
__device__ int g_off[NN + 1];
__device__ int g_cur[NN];
__device__ int g_esrc[EE];
__device__ int g_erel[EE];

// ---------------- helpers ----------------
__device__ __forceinline__ uint32_t smem_u32(const void* p) {
    uint32_t a;
    asm("{ .reg .u64 t; cvta.to.shared.u64 t, %1; cvt.u32.u64 %0, t; }" : "=r"(a) : "l"(p));
    return a;
}
__device__ __forceinline__ void ldsm4(uint32_t* r, uint32_t a) {
    asm volatile("ldmatrix.sync.aligned.m8n8.x4.shared.b16 {%0,%1,%2,%3}, [%4];"
                 : "=r"(r[0]), "=r"(r[1]), "=r"(r[2]), "=r"(r[3]) : "r"(a));
}
__device__ __forceinline__ void ldsm4t(uint32_t* r, uint32_t a) {
    asm volatile("ldmatrix.sync.aligned.m8n8.x4.trans.shared.b16 {%0,%1,%2,%3}, [%4];"
                 : "=r"(r[0]), "=r"(r[1]), "=r"(r[2]), "=r"(r[3]) : "r"(a));
}
__device__ __forceinline__ void mma16816(float* c, const uint32_t* a, uint32_t b0, uint32_t b1) {
    asm volatile(
        "mma.sync.aligned.m16n8k16.row.col.f32.bf16.bf16.f32 "
        "{%0,%1,%2,%3}, {%4,%5,%6,%7}, {%8,%9}, {%0,%1,%2,%3};"
        : "+f"(c[0]), "+f"(c[1]), "+f"(c[2]), "+f"(c[3])
        : "r"(a[0]), "r"(a[1]), "r"(a[2]), "r"(a[3]), "r"(b0), "r"(b1));
}
__device__ __forceinline__ void cpasync16(uint32_t sa, const void* gp) {
    asm volatile("cp.async.cg.shared.global [%0], [%1], 16;" :: "r"(sa), "l"(gp));
}

// ---------------- CSR build ----------------
__global__ void k_count(const int* __restrict__ eidx) {
    int e = blockIdx.x * blockDim.x + threadIdx.x;
    if (e < EE) atomicAdd(&g_deg[eidx[EE + e]], 1);
}
__global__ void k_scan() {
    __shared__ int part[256];
    int t = threadIdx.x;
    const int PER = 40;
    int base = t * PER;
    int s = 0;
    for (int i = 0; i < PER; i++) {
        int idx = base + i;
        if (idx < NN) s += g_deg[idx];
    }
    part[t] = s;
    __syncthreads();
    for (int off = 1; off < 256; off <<= 1) {
        int v = (t >= off) ? part[t - off] : 0;
        __syncthreads();
        part[t] += v;
        __syncthreads();
    }
    int run = (t == 0) ? 0 : part[t - 1];
    for (int i = 0; i < PER; i++) {
        int idx = base + i;
        if (idx < NN) {
            g_off[idx] = run;
            g_cur[idx] = run;
            run += g_deg[idx];
        }
    }
    if (t == 255) g_off[NN] = part[255];
}
__global__ void k_fill(const int* __restrict__ eidx, const int* __restrict__ etype) {
    int e = blockIdx.x * blockDim.x + threadIdx.x;
    if (e < EE) {
        int t = eidx[EE + e];
        int p = atomicAdd(&g_cur[t], 1);
        g_esrc[p] = eidx[e];
        g_erel[p] = etype[e];
    }
}

// ---------------- fused prep: W transpose+split, X split, coeff split ----------------
#define NB_W 1358   // (KPAD/32) * 7
#define NB_X 7813   // ceil(NN*DD / 256)
#define NB_C 54     // ceil(RR*BB / 256)
__global__ void k_prep(const float* __restrict__ w, const float* __restrict__ sw,
                       const float* __restrict__ x, const float* __restrict__ coeff) {
    int bw = blockIdx.x, tid = threadIdx.x;
    if (bw < NB_W) {
        __shared__ float tile[32][33];
        int k0 = (bw % 194) * 32;
        int n0 = (bw / 194) * 32;
        int tx = tid & 31, ty = tid >> 5;
#pragma unroll
        for (int s = 0; s < 4; s++) {
            int k = k0 + ty + 8 * s;
            int n = n0 + tx;
            float v = 0.f;
            if (n < DD) {
                if (k < 6000)      v = w[(size_t)k * DD + n];
                else if (k < KTOT) v = sw[(size_t)(k - 6000) * DD + n];
            }
            tile[ty + 8 * s][tx] = v;
        }
        __syncthreads();
#pragma unroll
        for (int s = 0; s < 4; s++) {
            int n = n0 + ty + 8 * s;
            int k = k0 + tx;
            if (n < DD) {
                float v = tile[tx][ty + 8 * s];
                __nv_bfloat16 h = __float2bfloat16(v);
                g_Bh[(size_t)n * KPAD + k] = h;
                g_Bl[(size_t)n * KPAD + k] = __float2bfloat16(v - __bfloat162float(h));
            }
        }
    } else if (bw < NB_W + NB_X) {
        int idx = (bw - NB_W) * 256 + tid;
        if (idx < NN * DD) {
            float v = x[idx];
            __nv_bfloat16 h = __float2bfloat16(v);
            g_Xh[idx] = h;
            g_Xl[idx] = __float2bfloat16(v - __bfloat162float(h));
        }
    } else {
        int idx = (bw - NB_W - NB_X) * 256 + tid;
        if (idx < RR * BB) {
            int r = idx / BB, b = idx - r * BB;
            float v = coeff[idx];
            __nv_bfloat16 h = __float2bfloat16(v);
            g_Crh[r * 32 + b] = h;
            g_Crl[r * 32 + b] = __float2bfloat16(v - __bfloat162float(h));
        }
    }
}

// ---------------- tensor-core aggregation ----------------
// Per node: H^T(208x32) = Xg^T(208 x deg) @ Cg(deg x 32), 3-term bf16 split.
// A frags from gathered X rows (16 edges x 200 bf16) via ldmatrix.trans,
// B frags from gathered coeff rows (16 edges x 32 bf16) via ldmatrix.trans.
#define AT   128
#define RSX  432           // 416 data + 16 pad; 8-row stride pattern conflict-free
#define XARR 6912          // 16 * RSX
#define XBUF 13824         // 2 arrays (hi, lo)
#define RSC  80
#define CARR 1280          // 16 * RSC
#define CBUF 2560

__global__ __launch_bounds__(AT) void k_agg(const float* __restrict__ x) {
    __shared__ __align__(16) char sX[2 * XBUF];
    __shared__ __align__(16) char sC[2 * CBUF];
    __shared__ int sSrc[2][16], sRel[2][16];
    uint32_t sxa = smem_u32(sX), sca = smem_u32(sC);
    int tid = threadIdx.x, lane = tid & 31, w = tid >> 5;
    int n = blockIdx.x;
    int start = g_off[n], end = g_off[n + 1];
    int deg = end - start;
    float inv = 1.0f / (float)(deg > 1 ? deg : 1);
    int chunks = (deg + 15) >> 4;
    int mtcnt = (w == 3) ? 4 : 3;    // m-tiles 3w .. 3w+mtcnt-1 (13 tiles over 208 d)

    // zero X staging once (pad cols 200-207 + row pad stay zero forever)
    for (int i = tid * 16; i < 2 * XBUF; i += AT * 16)
        *(uint4*)(sX + i) = make_uint4(0, 0, 0, 0);

    float acc[4][4][4];
#pragma unroll
    for (int i = 0; i < 4; i++)
#pragma unroll
        for (int j = 0; j < 4; j++)
#pragma unroll
            for (int q = 0; q < 4; q++) acc[i][j][q] = 0.f;

    auto meta = [&](int c, int buf) {
        if (tid < 16) {
            int e = start + c * 16 + tid;
            if (e < end) { sSrc[buf][tid] = g_esrc[e]; sRel[buf][tid] = g_erel[e]; }
            else         { sSrc[buf][tid] = 0;         sRel[buf][tid] = RR; }   // zero coeff row
        }
    };
    auto issue = [&](int buf) {
        const char* xs[2] = {(const char*)g_Xh, (const char*)g_Xl};
        const char* cs[2] = {(const char*)g_Crh, (const char*)g_Crl};
#pragma unroll
        for (int i = 0; i < 8; i++) {
            int t = tid + i * AT;
            if (t < 800) {
                int arr = t >= 400;
                int rem = t - arr * 400;
                int r = rem / 25, q = rem - r * 25;
                uint32_t sa = sxa + buf * XBUF + arr * XARR + r * RSX + q * 16;
                cpasync16(sa, xs[arr] + (size_t)sSrc[buf][r] * 400 + q * 16);
            } else if (t < 928) {
                int t2 = t - 800;
                int arr = t2 >= 64;
                int rem = t2 - arr * 64;
                int r = rem >> 2, q = rem & 3;
                uint32_t sa = sca + buf * CBUF + arr * CARR + r * RSC + q * 16;
                cpasync16(sa, cs[arr] + (size_t)sRel[buf][r] * 64 + q * 16);
            }
        }
        asm volatile("cp.async.commit_group;");
    };

    meta(0, 0);
    __syncthreads();                 // zero + meta visible
    if (chunks > 0) issue(0);

    int j = lane >> 3;
    int rowA = (lane & 7) + (j >> 1) * 8;   // A: j&1 -> m-half, j>>1 -> k-half
    int cbA  = (j & 1) * 16;
    int rowB = (lane & 7) + (j & 1) * 8;    // B: j&1 -> k-half, j>>1 -> n-half
    int cbB  = (j >> 1) * 16;

    for (int c = 0; c < chunks; c++) {
        int buf = c & 1;
        if (c + 1 < chunks) {
            meta(c + 1, buf ^ 1);
            __syncthreads();         // meta visible; prev compute done before overwrite
            issue(buf ^ 1);
            asm volatile("cp.async.wait_group 1;");
        } else {
            asm volatile("cp.async.wait_group 0;");
        }
        __syncthreads();             // chunk c data visible to all warps

        uint32_t bh[2][4], bl[2][4];
        {
            uint32_t base = sca + buf * CBUF + rowB * RSC + cbB;
            ldsm4t(bh[0], base);            // n-tiles 0,1
            ldsm4t(bh[1], base + 32);       // n-tiles 2,3
            ldsm4t(bl[0], base + CARR);
            ldsm4t(bl[1], base + CARR + 32);
        }
#pragma unroll
        for (int mtl = 0; mtl < 4; mtl++) {
            if (mtl >= mtcnt) break;
            int mt = 3 * w + mtl;
            uint32_t abase = sxa + buf * XBUF + rowA * RSX + mt * 32 + cbA;
            uint32_t ah[4], al[4];
            ldsm4t(ah, abase);
            ldsm4t(al, abase + XARR);
#pragma unroll
            for (int nt = 0; nt < 4; nt++)
                mma16816(acc[mtl][nt], ah, bh[nt >> 1][(nt & 1) * 2], bh[nt >> 1][(nt & 1) * 2 + 1]);
#pragma unroll
            for (int nt = 0; nt < 4; nt++)
                mma16816(acc[mtl][nt], al, bh[nt >> 1][(nt & 1) * 2], bh[nt >> 1][(nt & 1) * 2 + 1]);
#pragma unroll
            for (int nt = 0; nt < 4; nt++)
                mma16816(acc[mtl][nt], ah, bl[nt >> 1][(nt & 1) * 2], bl[nt >> 1][(nt & 1) * 2 + 1]);
        }
    }

    // epilogue: scale by inv, split to bf16 hi/lo, scatter into g_Ah/g_Al row n
    size_t rowb = (size_t)n * KPAD;
#pragma unroll
    for (int mtl = 0; mtl < 4; mtl++) {
        if (mtl >= mtcnt) break;
        int mt = 3 * w + mtl;
        int d0 = mt * 16 + (lane >> 2);
#pragma unroll
        for (int nt = 0; nt < 4; nt++) {
            int b0 = nt * 8 + (lane & 3) * 2;
#pragma unroll
            for (int q = 0; q < 4; q++) {
                int d = d0 + (q >> 1) * 8;
                int b = b0 + (q & 1);
                if (b < BB && d < DD) {
                    float v = acc[mtl][nt][q] * inv;
                    __nv_bfloat16 h = __float2bfloat16(v);
                    g_Ah[rowb + b * DD + d] = h;
                    g_Al[rowb + b * DD + d] = __float2bfloat16(v - __bfloat162float(h));
                }
            }
        }
    }
    if (tid < DD / 2) {   // self-loop K-columns 6000..6199
        float2 xv = *(const float2*)(x + (size_t)n * DD + 2 * tid);
        __nv_bfloat16 hx = __float2bfloat16(xv.x), hy = __float2bfloat16(xv.y);
        *(__nv_bfloat162*)&g_Ah[rowb + 6000 + 2 * tid] = __nv_bfloat162(hx, hy);
        __nv_bfloat16 lx = __float2bfloat16(xv.x - __bfloat162float(hx));
        __nv_bfloat16 ly = __float2bfloat16(xv.y - __bfloat162float(hy));
        *(__nv_bfloat162*)&g_Al[rowb + 6000 + 2 * tid] = __nv_bfloat162(lx, ly);
    }
}

// ---------------- persistent bf16 3-term MMA GEMM (unchanged from R6) ----------------
#define GT     256
#define RS     80
#define A_ARR  10240
#define B_ARR  17920
#define OFF_B  20480
#define STAGE  56320
#define SMEM_G (2 * STAGE)
#define GRID_G 152

__global__ __launch_bounds__(GT, 1) void k_gemm(const float* __restrict__ bias,
                                                float* __restrict__ out) {
    extern __shared__ char smem[];
    uint32_t sb = smem_u32(smem);
    int tid = threadIdx.x, lane = tid & 31, wid = tid >> 5;
    int wm = wid & 3, wn = wid >> 2;

    const char* gA[2] = {(const char*)g_Ah, (const char*)g_Al};
    const char* gB[2] = {(const char*)g_Bh, (const char*)g_Bl};

    int ri = lane & 7, mi = lane >> 3;
    uint32_t aOff = (uint32_t)((wm * 32 + ri + (mi & 1) * 8) * RS + (mi >> 1) * 16);
    uint32_t bOff = (uint32_t)(OFF_B + (wn * 112 + ri + ((mi >> 1) & 1) * 8) * RS + (mi & 1) * 16);
    int g = lane >> 2, tg = lane & 3;

    for (int u = blockIdx.x; u < NUNITS; u += GRID_G) {
        int mt = u % NMT;
        int ks = u / NMT;
        int m0 = mt * 128;
        int c0 = (NCHTOT * ks) >> 4;
        int c1 = (NCHTOT * (ks + 1)) >> 4;

        float acc[2][14][4];
#pragma unroll
        for (int i = 0; i < 2; i++)
#pragma unroll
            for (int jj = 0; jj < 14; jj++)
#pragma unroll
                for (int q = 0; q < 4; q++) acc[i][jj][q] = 0.f;

        auto issue = [&](int c, int buf) {
            uint32_t st = sb + buf * STAGE;
            size_t kb2 = (size_t)c * 64;
#pragma unroll
            for (int i = 0; i < 11; i++) {
                int t = tid + i * GT;
                uint32_t sa;
                const char* gp;
                if (t < 1024) {
                    int arr = t >> 9, rem = t & 511, r = rem >> 2, q = rem & 3;
                    sa = st + arr * A_ARR + r * RS + q * 16;
                    gp = gA[arr] + (size_t)(m0 + r) * (KPAD * 2) + kb2 + q * 16;
                } else {
                    int t2 = t - 1024;
                    int arr = t2 / 896, rem = t2 % 896, r = rem >> 2, q = rem & 3;
                    sa = st + OFF_B + arr * B_ARR + r * RS + q * 16;
                    gp = gB[arr] + (size_t)r * (KPAD * 2) + kb2 + q * 16;
                }
                cpasync16(sa, gp);
            }
            asm volatile("cp.async.commit_group;");
        };

        issue(c0, 0);
        for (int c = c0; c < c1; c++) {
            int buf = (c - c0) & 1;
            if (c + 1 < c1) {
                issue(c + 1, buf ^ 1);
                asm volatile("cp.async.wait_group 1;");
            } else {
                asm volatile("cp.async.wait_group 0;");
            }
            __syncthreads();

            uint32_t st = sb + buf * STAGE;
#pragma unroll
            for (int kk = 0; kk < 2; kk++) {
                uint32_t ka = st + aOff + kk * 32;
                uint32_t ah0[4], ah1[4], al0[4], al1[4];
                ldsm4(ah0, ka);
                ldsm4(ah1, ka + 16 * RS);
                ldsm4(al0, ka + A_ARR);
                ldsm4(al1, ka + A_ARR + 16 * RS);
                uint32_t kb = st + bOff + kk * 32;
#pragma unroll
                for (int nf = 0; nf < 7; nf++) {
                    uint32_t bh[4], bl[4];
                    ldsm4(bh, kb + nf * (16 * RS));
                    ldsm4(bl, kb + nf * (16 * RS) + B_ARR);
                    mma16816(acc[0][2 * nf],     ah0, bh[0], bh[1]);
                    mma16816(acc[1][2 * nf],     ah1, bh[0], bh[1]);
                    mma16816(acc[0][2 * nf + 1], ah0, bh[2], bh[3]);
                    mma16816(acc[1][2 * nf + 1], ah1, bh[2], bh[3]);
                    mma16816(acc[0][2 * nf],     ah0, bl[0], bl[1]);
                    mma16816(acc[1][2 * nf],     ah1, bl[0], bl[1]);
                    mma16816(acc[0][2 * nf + 1], ah0, bl[2], bl[3]);
                    mma16816(acc[1][2 * nf + 1], ah1, bl[2], bl[3]);
                    mma16816(acc[0][2 * nf],     al0, bh[0], bh[1]);
                    mma16816(acc[1][2 * nf],     al1, bh[0], bh[1]);
                    mma16816(acc[0][2 * nf + 1], al0, bh[2], bh[3]);
                    mma16816(acc[1][2 * nf + 1], al1, bh[2], bh[3]);
                }
            }
            __syncthreads();
        }

#pragma unroll
        for (int mf = 0; mf < 2; mf++) {
            int r0 = m0 + wm * 32 + mf * 16 + g;
            int r1 = r0 + 8;
#pragma unroll
            for (int nf = 0; nf < 14; nf++) {
                int col = wn * 112 + nf * 8 + tg * 2;
                if (col < DD) {
                    float b0 = 0.f, b1 = 0.f;
                    if (ks == 0) { b0 = bias[col]; b1 = bias[col + 1]; }
                    if (r0 < NN) {
                        atomicAdd(&out[(size_t)r0 * DD + col],     acc[mf][nf][0] + b0);
                        atomicAdd(&out[(size_t)r0 * DD + col + 1], acc[mf][nf][1] + b1);
                    }
                    if (r1 < NN) {
                        atomicAdd(&out[(size_t)r1 * DD + col],     acc[mf][nf][2] + b0);
                        atomicAdd(&out[(size_t)r1 * DD + col + 1], acc[mf][nf][3] + b1);
                    }
                }
            }
        }
    }
}

extern "C" void kernel_launch(void* const* d_in, const int* in_sizes, int n_in,
                              void* d_out, int out_size) {
    const float* x      = (const float*)d_in[0];
    const float* weight = (const float*)d_in[1];
    const float* coeff  = (const float*)d_in[2];
    const float* selfw  = (const float*)d_in[3];
    const float* bias   = (const float*)d_in[4];
    const int*   eidx   = (const int*)d_in[5];
    const int*   etype  = (const int*)d_in[6];
    float*       out    = (float*)d_out;

    static void* p_deg = nullptr;
    if (!p_deg) {
        cudaGetSymbolAddress(&p_deg, g_deg);
        cudaFuncSetAttribute(k_gemm, cudaFuncAttributeMaxDynamicSharedMemorySize, SMEM_G);
    }

    cudaMemsetAsync(p_deg, 0, NN * sizeof(int));                       // launch 1
    k_count<<<(EE + 255) / 256, 256>>>(eidx);                          // 2
    k_scan<<<1, 256>>>();                                              // 3
    k_fill<<<(EE + 255) / 256, 256>>>(eidx, etype);                    // 4
    k_prep<<<NB_W + NB_X + NB_C, 256>>>(weight, selfw, x, coeff);      // 5
    k_agg<<<NN, AT>>>(x);                                              // 6  <- profiled
    cudaMemsetAsync(out, 0, (size_t)NN * DD * sizeof(float));          // 7
    k_gemm<<<GRID_G, GT, SMEM_G>>>(bias, out);                         // 8
}

// round 9
// speedup vs baseline: 1.2796x; 1.2796x over previous
#include <cuda_runtime.h>
#include <cuda_fp16.h>
#include <cstdint>

#define NN   10000
#define EE   320000
#define RR   460
#define BB   30
#define DD   200
#define KTOT 6200
#define KPAD 6208            // multiple of 64
#define MPAD 10112           // 79 * 128
#define NPAD 224
#define NCHTOT 194           // KPAD / 32
#define NKSL  16
#define NMT   79
#define NUNITS (NMT * NKSL)

// ---- device scratch (zero-initialized; pads never written -> stay 0) ----
__device__ __align__(256) __half g_Ah[(size_t)MPAD * KPAD];
__device__ __align__(256) __half g_Al[(size_t)MPAD * KPAD];
__device__ __align__(256) __half g_Bh[(size_t)NPAD * KPAD];   // B^T: n-major rows, k cols
__device__ int g_deg[NN];
__device__ int g_off[NN + 1];
__device__ int g_cur[NN];
__device__ int g_esrc[EE];
__device__ int g_erel[EE];

// ---------------- helpers ----------------
__device__ __forceinline__ uint32_t smem_u32(const void* p) {
    uint32_t a;
    asm("{ .reg .u64 t; cvta.to.shared.u64 t, %1; cvt.u32.u64 %0, t; }" : "=r"(a) : "l"(p));
    return a;
}
__device__ __forceinline__ void ldsm4(uint32_t* r, uint32_t a) {
    asm volatile("ldmatrix.sync.aligned.m8n8.x4.shared.b16 {%0,%1,%2,%3}, [%4];"
                 : "=r"(r[0]), "=r"(r[1]), "=r"(r[2]), "=r"(r[3]) : "r"(a));
}
__device__ __forceinline__ void mma16816(float* c, const uint32_t* a, uint32_t b0, uint32_t b1) {
    asm volatile(
        "mma.sync.aligned.m16n8k16.row.col.f32.f16.f16.f32 "
        "{%0,%1,%2,%3}, {%4,%5,%6,%7}, {%8,%9}, {%0,%1,%2,%3};"
        : "+f"(c[0]), "+f"(c[1]), "+f"(c[2]), "+f"(c[3])
        : "r"(a[0]), "r"(a[1]), "r"(a[2]), "r"(a[3]), "r"(b0), "r"(b1));
}
__device__ __forceinline__ void cpasync16(uint32_t sa, const void* gp) {
    asm volatile("cp.async.cg.shared.global [%0], [%1], 16;" :: "r"(sa), "l"(gp));
}

// ---------------- CSR build ----------------
__global__ void k_count(const int* __restrict__ eidx) {
    int e = blockIdx.x * blockDim.x + threadIdx.x;
    if (e < EE) atomicAdd(&g_deg[eidx[EE + e]], 1);
}
__global__ void k_scan() {
    __shared__ int part[256];
    int t = threadIdx.x;
    const int PER = 40;
    int base = t * PER;
    int s = 0;
    for (int i = 0; i < PER; i++) {
        int idx = base + i;
        if (idx < NN) s += g_deg[idx];
    }
    part[t] = s;
    __syncthreads();
    for (int off = 1; off < 256; off <<= 1) {
        int v = (t >= off) ? part[t - off] : 0;
        __syncthreads();
        part[t] += v;
        __syncthreads();
    }
    int run = (t == 0) ? 0 : part[t - 1];
    for (int i = 0; i < PER; i++) {
        int idx = base + i;
        if (idx < NN) {
            g_off[idx] = run;
            g_cur[idx] = run;
            run += g_deg[idx];
        }
    }
    if (t == 255) g_off[NN] = part[255];
}

// ---------------- fused: CSR fill + W transpose/split + out zeroing ----------------
#define NB_FILL 1250
#define NB_W    1358         // (KPAD/32) * 7
#define NB_O    7813         // ceil(NN*DD/256)
__global__ void k_misc(const int* __restrict__ eidx, const int* __restrict__ etype,
                       const float* __restrict__ w, const float* __restrict__ sw,
                       float* __restrict__ out) {
    int bw = blockIdx.x, tid = threadIdx.x;
    if (bw < NB_FILL) {
        int e = bw * 256 + tid;
        if (e < EE) {
            int t = eidx[EE + e];
            int p = atomicAdd(&g_cur[t], 1);
            g_esrc[p] = eidx[e];
            g_erel[p] = etype[e];
        }
    } else if (bw < NB_FILL + NB_W) {
        __shared__ float tile[32][33];
        int b = bw - NB_FILL;
        int k0 = (b % 194) * 32;
        int n0 = (b / 194) * 32;
        int tx = tid & 31, ty = tid >> 5;
#pragma unroll
        for (int s = 0; s < 4; s++) {
            int k = k0 + ty + 8 * s;
            int n = n0 + tx;
            float v = 0.f;
            if (n < DD) {
                if (k < 6000)      v = w[(size_t)k * DD + n];
                else if (k < KTOT) v = sw[(size_t)(k - 6000) * DD + n];
            }
            tile[ty + 8 * s][tx] = v;
        }
        __syncthreads();
#pragma unroll
        for (int s = 0; s < 4; s++) {
            int n = n0 + ty + 8 * s;
            int k = k0 + tx;
            if (n < DD) g_Bh[(size_t)n * KPAD + k] = __float2half(tile[tx][ty + 8 * s]);
        }
    } else {
        int i = (bw - NB_FILL - NB_W) * 256 + tid;
        if (i < NN * DD) out[i] = 0.f;
    }
}

// ---------------- aggregation -> fp16 hi/lo A rows (R6 structure) ----------------
#define AGG_T 224
#define EB    32
__global__ __launch_bounds__(AGG_T) void k_agg(const float* __restrict__ x,
                                               const float* __restrict__ coeff) {
    __shared__ float sC[EB][32];
    __shared__ int   sSrc[EB];
    __shared__ int   sRel[EB];
    int n   = blockIdx.x;
    int tid = threadIdx.x;
    int start = g_off[n], end = g_off[n + 1];
    int deg = end - start;
    float inv = 1.0f / (float)(deg > 1 ? deg : 1);

    float acc[32];
#pragma unroll
    for (int b = 0; b < 32; b++) acc[b] = 0.f;

    int d = tid;
    bool active = d < DD;
    for (int e0 = start; e0 < end; e0 += EB) {
        int nb = min(EB, end - e0);
        __syncthreads();
        if (tid < nb) { sSrc[tid] = g_esrc[e0 + tid]; sRel[tid] = g_erel[e0 + tid]; }
        __syncthreads();
        for (int i = tid; i < nb * 32; i += AGG_T) {
            int le = i >> 5, b = i & 31;
            sC[le][b] = (b < BB) ? coeff[sRel[le] * BB + b] : 0.f;
        }
        __syncthreads();
        if (active) {
            int le = 0;
            for (; le + 4 <= nb; le += 4) {
                float xv0 = x[(size_t)sSrc[le]     * DD + d];
                float xv1 = x[(size_t)sSrc[le + 1] * DD + d];
                float xv2 = x[(size_t)sSrc[le + 2] * DD + d];
                float xv3 = x[(size_t)sSrc[le + 3] * DD + d];
                const float4* c0 = (const float4*)sC[le];
                const float4* c1 = (const float4*)sC[le + 1];
                const float4* c2 = (const float4*)sC[le + 2];
                const float4* c3 = (const float4*)sC[le + 3];
#pragma unroll
                for (int q = 0; q < 8; q++) {
                    float4 a0 = c0[q], a1 = c1[q], a2 = c2[q], a3 = c3[q];
                    acc[4*q+0] = fmaf(a0.x, xv0, acc[4*q+0]);
                    acc[4*q+1] = fmaf(a0.y, xv0, acc[4*q+1]);
                    acc[4*q+2] = fmaf(a0.z, xv0, acc[4*q+2]);
                    acc[4*q+3] = fmaf(a0.w, xv0, acc[4*q+3]);
                    acc[4*q+0] = fmaf(a1.x, xv1, acc[4*q+0]);
                    acc[4*q+1] = fmaf(a1.y, xv1, acc[4*q+1]);
                    acc[4*q+2] = fmaf(a1.z, xv1, acc[4*q+2]);
                    acc[4*q+3] = fmaf(a1.w, xv1, acc[4*q+3]);
                    acc[4*q+0] = fmaf(a2.x, xv2, acc[4*q+0]);
                    acc[4*q+1] = fmaf(a2.y, xv2, acc[4*q+1]);
                    acc[4*q+2] = fmaf(a2.z, xv2, acc[4*q+2]);
                    acc[4*q+3] = fmaf(a2.w, xv2, acc[4*q+3]);
                    acc[4*q+0] = fmaf(a3.x, xv3, acc[4*q+0]);
                    acc[4*q+1] = fmaf(a3.y, xv3, acc[4*q+1]);
                    acc[4*q+2] = fmaf(a3.z, xv3, acc[4*q+2]);
                    acc[4*q+3] = fmaf(a3.w, xv3, acc[4*q+3]);
                }
            }
            for (; le < nb; le++) {
                float xv = x[(size_t)sSrc[le] * DD + d];
                const float4* cp = (const float4*)sC[le];
#pragma unroll
                for (int q = 0; q < 8; q++) {
                    float4 a = cp[q];
                    acc[4*q+0] = fmaf(a.x, xv, acc[4*q+0]);
                    acc[4*q+1] = fmaf(a.y, xv, acc[4*q+1]);
                    acc[4*q+2] = fmaf(a.z, xv, acc[4*q+2]);
                    acc[4*q+3] = fmaf(a.w, xv, acc[4*q+3]);
                }
            }
        }
    }
    if (active) {
        size_t row = (size_t)n * KPAD;
#pragma unroll
        for (int b = 0; b < BB; b++) {
            float v = acc[b] * inv;
            __half h = __float2half(v);
            g_Ah[row + b * DD + d] = h;
            g_Al[row + b * DD + d] = __float2half(v - __half2float(h));
        }
        float v = x[(size_t)n * DD + d];
        __half h = __float2half(v);
        g_Ah[row + 6000 + d] = h;
        g_Al[row + 6000 + d] = __float2half(v - __half2float(h));
    }
}

// ---------------- persistent fp16 2-term MMA GEMM ----------------
// 152 CTAs, 1264 units (79 mtiles x 16 kslices), m128 x n224, atomic epilogue.
// out = (Ah + Al) @ Bh^T ; dropped-Bl error ~2^-12 rel.
#define GT     256
#define RS     80            // 64B data + 16B pad per row (conflict-free ldmatrix)
#define A_ARR  10240         // 128*RS
#define B_ARR  17920         // 224*RS
#define OFF_B  20480         // 2*A_ARR
#define STAGE  38400         // 2*A_ARR + B_ARR
#define SMEM_G (2 * STAGE)   // 76800
#define GRID_G 152

__global__ __launch_bounds__(GT, 1) void k_gemm(const float* __restrict__ bias,
                                                float* __restrict__ out) {
    extern __shared__ char smem[];
    uint32_t sb = smem_u32(smem);
    int tid = threadIdx.x, lane = tid & 31, wid = tid >> 5;
    int wm = wid & 3, wn = wid >> 2;

    const char* gA[2] = {(const char*)g_Ah, (const char*)g_Al};
    const char* gB = (const char*)g_Bh;

    int ri = lane & 7, mi = lane >> 3;
    uint32_t aOff = (uint32_t)((wm * 32 + ri + (mi & 1) * 8) * RS + (mi >> 1) * 16);
    uint32_t bOff = (uint32_t)(OFF_B + (wn * 112 + ri + ((mi >> 1) & 1) * 8) * RS + (mi & 1) * 16);
    int g = lane >> 2, tg = lane & 3;

    for (int u = blockIdx.x; u < NUNITS; u += GRID_G) {
        int mt = u % NMT;
        int ks = u / NMT;
        int m0 = mt * 128;
        int c0 = (NCHTOT * ks) >> 4;
        int c1 = (NCHTOT * (ks + 1)) >> 4;

        float acc[2][14][4];
#pragma unroll
        for (int i = 0; i < 2; i++)
#pragma unroll
            for (int jj = 0; jj < 14; jj++)
#pragma unroll
                for (int q = 0; q < 4; q++) acc[i][jj][q] = 0.f;

        // 1920 16B ops per chunk: A hi/lo 1024, B 896
        auto issue = [&](int c, int buf) {
            uint32_t st = sb + buf * STAGE;
            size_t kb2 = (size_t)c * 64;
#pragma unroll
            for (int i = 0; i < 8; i++) {
                int t = tid + i * GT;
                if (t < 1920) {
                    uint32_t sa;
                    const char* gp;
                    if (t < 1024) {
                        int arr = t >> 9, rem = t & 511, r = rem >> 2, q = rem & 3;
                        sa = st + arr * A_ARR + r * RS + q * 16;
                        gp = gA[arr] + (size_t)(m0 + r) * (KPAD * 2) + kb2 + q * 16;
                    } else {
                        int t2 = t - 1024;
                        int r = t2 >> 2, q = t2 & 3;
                        sa = st + OFF_B + r * RS + q * 16;
                        gp = gB + (size_t)r * (KPAD * 2) + kb2 + q * 16;
                    }
                    cpasync16(sa, gp);
                }
            }
            asm volatile("cp.async.commit_group;");
        };

        issue(c0, 0);
        for (int c = c0; c < c1; c++) {
            int buf = (c - c0) & 1;
            if (c + 1 < c1) {
                issue(c + 1, buf ^ 1);
                asm volatile("cp.async.wait_group 1;");
            } else {
                asm volatile("cp.async.wait_group 0;");
            }
            __syncthreads();

            uint32_t st = sb + buf * STAGE;
#pragma unroll
            for (int kk = 0; kk < 2; kk++) {
                uint32_t ka = st + aOff + kk * 32;
                uint32_t ah0[4], ah1[4], al0[4], al1[4];
                ldsm4(ah0, ka);
                ldsm4(ah1, ka + 16 * RS);
                ldsm4(al0, ka + A_ARR);
                ldsm4(al1, ka + A_ARR + 16 * RS);
                uint32_t kb = st + bOff + kk * 32;
#pragma unroll
                for (int nf = 0; nf < 7; nf++) {
                    uint32_t bh[4];
                    ldsm4(bh, kb + nf * (16 * RS));
                    mma16816(acc[0][2 * nf],     ah0, bh[0], bh[1]);
                    mma16816(acc[1][2 * nf],     ah1, bh[0], bh[1]);
                    mma16816(acc[0][2 * nf + 1], ah0, bh[2], bh[3]);
                    mma16816(acc[1][2 * nf + 1], ah1, bh[2], bh[3]);
                    mma16816(acc[0][2 * nf],     al0, bh[0], bh[1]);
                    mma16816(acc[1][2 * nf],     al1, bh[0], bh[1]);
                    mma16816(acc[0][2 * nf + 1], al0, bh[2], bh[3]);
                    mma16816(acc[1][2 * nf + 1], al1, bh[2], bh[3]);
                }
            }
            __syncthreads();
        }

        // epilogue: atomicAdd partials; kslice 0 also adds bias (out zeroed in k_misc)
#pragma unroll
        for (int mf = 0; mf < 2; mf++) {
            int r0 = m0 + wm * 32 + mf * 16 + g;
            int r1 = r0 + 8;
#pragma unroll
            for (int nf = 0; nf < 14; nf++) {
                int col = wn * 112 + nf * 8 + tg * 2;
                if (col < DD) {
                    float b0 = 0.f, b1 = 0.f;
                    if (ks == 0) { b0 = bias[col]; b1 = bias[col + 1]; }
                    if (r0 < NN) {
                        atomicAdd(&out[(size_t)r0 * DD + col],     acc[mf][nf][0] + b0);
                        atomicAdd(&out[(size_t)r0 * DD + col + 1], acc[mf][nf][1] + b1);
                    }
                    if (r1 < NN) {
                        atomicAdd(&out[(size_t)r1 * DD + col],     acc[mf][nf][2] + b0);
                        atomicAdd(&out[(size_t)r1 * DD + col + 1], acc[mf][nf][3] + b1);
                    }
                }
            }
        }
    }
}

extern "C" void kernel_launch(void* const* d_in, const int* in_sizes, int n_in,
                              void* d_out, int out_size) {
    const float* x      = (const float*)d_in[0];
    const float* weight = (const float*)d_in[1];
    const float* coeff  = (const float*)d_in[2];
    const float* selfw  = (const float*)d_in[3];
    const float* bias   = (const float*)d_in[4];
    const int*   eidx   = (const int*)d_in[5];
    const int*   etype  = (const int*)d_in[6];
    float*       out    = (float*)d_out;

    static void* p_deg = nullptr;
    if (!p_deg) {
        cudaGetSymbolAddress(&p_deg, g_deg);
        cudaFuncSetAttribute(k_gemm, cudaFuncAttributeMaxDynamicSharedMemorySize, SMEM_G);
    }

    cudaMemsetAsync(p_deg, 0, NN * sizeof(int));                            // 1
    k_count<<<(EE + 255) / 256, 256>>>(eidx);                               // 2
    k_scan<<<1, 256>>>();                                                   // 3
    k_misc<<<NB_FILL + NB_W + NB_O, 256>>>(eidx, etype, weight, selfw, out);// 4
    k_agg<<<NN, AGG_T>>>(x, coeff);                                         // 5
    k_gemm<<<GRID_G, GT, SMEM_G>>>(bias, out);                              // 6 <- profiled
}

// round 10
// speedup vs baseline: 1.5368x; 1.2010x over previous
#include <cuda_runtime.h>
#include <cuda_fp16.h>
#include <cstdint>

#define NN   10000
#define EE   320000
#define RR   460
#define BB   30
#define DD   200
#define KTOT 6200
#define KPAD 6208            // multiple of 64
#define MPAD 10112           // 79 * 128
#define NPAD 224
#define NCHTOT 194           // KPAD / 32
#define NKSL  16
#define NMT   79
#define NUNITS (NMT * NKSL)

// ---- device scratch (zero-initialized; pads never written -> stay 0) ----
__device__ __align__(256) __half g_Ah[(size_t)MPAD * KPAD];
__device__ __align__(256) __half g_Bh[(size_t)NPAD * KPAD];   // B^T: n-major rows, k cols
__device__ int g_deg[NN];
__device__ int g_off[NN + 1];
__device__ int g_cur[NN];
__device__ int g_esrc[EE];
__device__ int g_erel[EE];

// ---------------- helpers ----------------
__device__ __forceinline__ uint32_t smem_u32(const void* p) {
    uint32_t a;
    asm("{ .reg .u64 t; cvta.to.shared.u64 t, %1; cvt.u32.u64 %0, t; }" : "=r"(a) : "l"(p));
    return a;
}
__device__ __forceinline__ void ldsm4(uint32_t* r, uint32_t a) {
    asm volatile("ldmatrix.sync.aligned.m8n8.x4.shared.b16 {%0,%1,%2,%3}, [%4];"
                 : "=r"(r[0]), "=r"(r[1]), "=r"(r[2]), "=r"(r[3]) : "r"(a));
}
__device__ __forceinline__ void mma16816(float* c, const uint32_t* a, uint32_t b0, uint32_t b1) {
    asm volatile(
        "mma.sync.aligned.m16n8k16.row.col.f32.f16.f16.f32 "
        "{%0,%1,%2,%3}, {%4,%5,%6,%7}, {%8,%9}, {%0,%1,%2,%3};"
        : "+f"(c[0]), "+f"(c[1]), "+f"(c[2]), "+f"(c[3])
        : "r"(a[0]), "r"(a[1]), "r"(a[2]), "r"(a[3]), "r"(b0), "r"(b1));
}
__device__ __forceinline__ void cpasync16(uint32_t sa, const void* gp) {
    asm volatile("cp.async.cg.shared.global [%0], [%1], 16;" :: "r"(sa), "l"(gp));
}

// ---------------- CSR build ----------------
__global__ void k_count(const int* __restrict__ eidx) {
    int e = blockIdx.x * blockDim.x + threadIdx.x;
    if (e < EE) atomicAdd(&g_deg[eidx[EE + e]], 1);
}
__global__ void k_scan() {
    __shared__ int part[256];
    int t = threadIdx.x;
    const int PER = 40;
    int base = t * PER;
    int s = 0;
    for (int i = 0; i < PER; i++) {
        int idx = base + i;
        if (idx < NN) s += g_deg[idx];
    }
    part[t] = s;
    __syncthreads();
    for (int off = 1; off < 256; off <<= 1) {
        int v = (t >= off) ? part[t - off] : 0;
        __syncthreads();
        part[t] += v;
        __syncthreads();
    }
    int run = (t == 0) ? 0 : part[t - 1];
    for (int i = 0; i < PER; i++) {
        int idx = base + i;
        if (idx < NN) {
            g_off[idx] = run;
            g_cur[idx] = run;
            run += g_deg[idx];
        }
    }
    if (t == 255) g_off[NN] = part[255];
}

// ---------------- fused: CSR fill + W transpose + out zeroing ----------------
#define NB_FILL 1250
#define NB_W    1358         // (KPAD/32) * 7
#define NB_O    7813         // ceil(NN*DD/256)
__global__ void k_misc(const int* __restrict__ eidx, const int* __restrict__ etype,
                       const float* __restrict__ w, const float* __restrict__ sw,
                       float* __restrict__ out) {
    int bw = blockIdx.x, tid = threadIdx.x;
    if (bw < NB_FILL) {
        int e = bw * 256 + tid;
        if (e < EE) {
            int t = eidx[EE + e];
            int p = atomicAdd(&g_cur[t], 1);
            g_esrc[p] = eidx[e];
            g_erel[p] = etype[e];
        }
    } else if (bw < NB_FILL + NB_W) {
        __shared__ float tile[32][33];
        int b = bw - NB_FILL;
        int k0 = (b % 194) * 32;
        int n0 = (b / 194) * 32;
        int tx = tid & 31, ty = tid >> 5;
#pragma unroll
        for (int s = 0; s < 4; s++) {
            int k = k0 + ty + 8 * s;
            int n = n0 + tx;
            float v = 0.f;
            if (n < DD) {
                if (k < 6000)      v = w[(size_t)k * DD + n];
                else if (k < KTOT) v = sw[(size_t)(k - 6000) * DD + n];
            }
            tile[ty + 8 * s][tx] = v;
        }
        __syncthreads();
#pragma unroll
        for (int s = 0; s < 4; s++) {
            int n = n0 + ty + 8 * s;
            int k = k0 + tx;
            if (n < DD) g_Bh[(size_t)n * KPAD + k] = __float2half(tile[tx][ty + 8 * s]);
        }
    } else {
        int i = (bw - NB_FILL - NB_W) * 256 + tid;
        if (i < NN * DD) out[i] = 0.f;
    }
}

// ---------------- aggregation -> fp16 A rows ----------------
#define AGG_T 224
#define EB    32
__global__ __launch_bounds__(AGG_T) void k_agg(const float* __restrict__ x,
                                               const float* __restrict__ coeff) {
    __shared__ float sC[EB][32];
    __shared__ int   sSrc[EB];
    __shared__ int   sRel[EB];
    int n   = blockIdx.x;
    int tid = threadIdx.x;
    int start = g_off[n], end = g_off[n + 1];
    int deg = end - start;
    float inv = 1.0f / (float)(deg > 1 ? deg : 1);

    float acc[32];
#pragma unroll
    for (int b = 0; b < 32; b++) acc[b] = 0.f;

    int d = tid;
    bool active = d < DD;
    for (int e0 = start; e0 < end; e0 += EB) {
        int nb = min(EB, end - e0);
        __syncthreads();
        if (tid < nb) { sSrc[tid] = g_esrc[e0 + tid]; sRel[tid] = g_erel[e0 + tid]; }
        __syncthreads();
        for (int i = tid; i < nb * 32; i += AGG_T) {
            int le = i >> 5, b = i & 31;
            sC[le][b] = (b < BB) ? coeff[sRel[le] * BB + b] : 0.f;
        }
        __syncthreads();
        if (active) {
            int le = 0;
            for (; le + 4 <= nb; le += 4) {
                float xv0 = x[(size_t)sSrc[le]     * DD + d];
                float xv1 = x[(size_t)sSrc[le + 1] * DD + d];
                float xv2 = x[(size_t)sSrc[le + 2] * DD + d];
                float xv3 = x[(size_t)sSrc[le + 3] * DD + d];
                const float4* c0 = (const float4*)sC[le];
                const float4* c1 = (const float4*)sC[le + 1];
                const float4* c2 = (const float4*)sC[le + 2];
                const float4* c3 = (const float4*)sC[le + 3];
#pragma unroll
                for (int q = 0; q < 8; q++) {
                    float4 a0 = c0[q], a1 = c1[q], a2 = c2[q], a3 = c3[q];
                    acc[4*q+0] = fmaf(a0.x, xv0, acc[4*q+0]);
                    acc[4*q+1] = fmaf(a0.y, xv0, acc[4*q+1]);
                    acc[4*q+2] = fmaf(a0.z, xv0, acc[4*q+2]);
                    acc[4*q+3] = fmaf(a0.w, xv0, acc[4*q+3]);
                    acc[4*q+0] = fmaf(a1.x, xv1, acc[4*q+0]);
                    acc[4*q+1] = fmaf(a1.y, xv1, acc[4*q+1]);
                    acc[4*q+2] = fmaf(a1.z, xv1, acc[4*q+2]);
                    acc[4*q+3] = fmaf(a1.w, xv1, acc[4*q+3]);
                    acc[4*q+0] = fmaf(a2.x, xv2, acc[4*q+0]);
                    acc[4*q+1] = fmaf(a2.y, xv2, acc[4*q+1]);
                    acc[4*q+2] = fmaf(a2.z, xv2, acc[4*q+2]);
                    acc[4*q+3] = fmaf(a2.w, xv2, acc[4*q+3]);
                    acc[4*q+0] = fmaf(a3.x, xv3, acc[4*q+0]);
                    acc[4*q+1] = fmaf(a3.y, xv3, acc[4*q+1]);
                    acc[4*q+2] = fmaf(a3.z, xv3, acc[4*q+2]);
                    acc[4*q+3] = fmaf(a3.w, xv3, acc[4*q+3]);
                }
            }
            for (; le < nb; le++) {
                float xv = x[(size_t)sSrc[le] * DD + d];
                const float4* cp = (const float4*)sC[le];
#pragma unroll
                for (int q = 0; q < 8; q++) {
                    float4 a = cp[q];
                    acc[4*q+0] = fmaf(a.x, xv, acc[4*q+0]);
                    acc[4*q+1] = fmaf(a.y, xv, acc[4*q+1]);
                    acc[4*q+2] = fmaf(a.z, xv, acc[4*q+2]);
                    acc[4*q+3] = fmaf(a.w, xv, acc[4*q+3]);
                }
            }
        }
    }
    if (active) {
        size_t row = (size_t)n * KPAD;
#pragma unroll
        for (int b = 0; b < BB; b++)
            g_Ah[row + b * DD + d] = __float2half(acc[b] * inv);
        g_Ah[row + 6000 + d] = __float2half(x[(size_t)n * DD + d]);
    }
}

// ---------------- persistent fp16 1-term MMA GEMM ----------------
// 152 CTAs, 1264 units (79 mtiles x 16 kslices), m128 x n224, atomic epilogue.
// out = Ah @ Bh^T ; fp16 RN error on A and B ~2^-11 each (random, ~2.6e-4 combined).
#define GT     256
#define RS     80            // 64B data + 16B pad per row (conflict-free ldmatrix)
#define A_ARR  10240         // 128*RS
#define B_ARR  17920         // 224*RS
#define OFF_B  10240         // A_ARR
#define STAGE  28160         // A_ARR + B_ARR
#define SMEM_G (2 * STAGE)   // 56320
#define GRID_G 152

__global__ __launch_bounds__(GT, 1) void k_gemm(const float* __restrict__ bias,
                                                float* __restrict__ out) {
    extern __shared__ char smem[];
    uint32_t sb = smem_u32(smem);
    int tid = threadIdx.x, lane = tid & 31, wid = tid >> 5;
    int wm = wid & 3, wn = wid >> 2;

    const char* gA = (const char*)g_Ah;
    const char* gB = (const char*)g_Bh;

    int ri = lane & 7, mi = lane >> 3;
    uint32_t aOff = (uint32_t)((wm * 32 + ri + (mi & 1) * 8) * RS + (mi >> 1) * 16);
    uint32_t bOff = (uint32_t)(OFF_B + (wn * 112 + ri + ((mi >> 1) & 1) * 8) * RS + (mi & 1) * 16);
    int g = lane >> 2, tg = lane & 3;

    for (int u = blockIdx.x; u < NUNITS; u += GRID_G) {
        int mt = u % NMT;
        int ks = u / NMT;
        int m0 = mt * 128;
        int c0 = (NCHTOT * ks) >> 4;
        int c1 = (NCHTOT * (ks + 1)) >> 4;

        float acc[2][14][4];
#pragma unroll
        for (int i = 0; i < 2; i++)
#pragma unroll
            for (int jj = 0; jj < 14; jj++)
#pragma unroll
                for (int q = 0; q < 4; q++) acc[i][jj][q] = 0.f;

        // 1408 16B ops per chunk: A 512, B 896
        auto issue = [&](int c, int buf) {
            uint32_t st = sb + buf * STAGE;
            size_t kb2 = (size_t)c * 64;
#pragma unroll
            for (int i = 0; i < 6; i++) {
                int t = tid + i * GT;
                if (t < 1408) {
                    uint32_t sa;
                    const char* gp;
                    if (t < 512) {
                        int r = t >> 2, q = t & 3;
                        sa = st + r * RS + q * 16;
                        gp = gA + (size_t)(m0 + r) * (KPAD * 2) + kb2 + q * 16;
                    } else {
                        int t2 = t - 512;
                        int r = t2 >> 2, q = t2 & 3;
                        sa = st + OFF_B + r * RS + q * 16;
                        gp = gB + (size_t)r * (KPAD * 2) + kb2 + q * 16;
                    }
                    cpasync16(sa, gp);
                }
            }
            asm volatile("cp.async.commit_group;");
        };

        issue(c0, 0);
        for (int c = c0; c < c1; c++) {
            int buf = (c - c0) & 1;
            if (c + 1 < c1) {
                issue(c + 1, buf ^ 1);
                asm volatile("cp.async.wait_group 1;");
            } else {
                asm volatile("cp.async.wait_group 0;");
            }
            __syncthreads();

            uint32_t st = sb + buf * STAGE;
#pragma unroll
            for (int kk = 0; kk < 2; kk++) {
                uint32_t ka = st + aOff + kk * 32;
                uint32_t ah0[4], ah1[4];
                ldsm4(ah0, ka);
                ldsm4(ah1, ka + 16 * RS);
                uint32_t kb = st + bOff + kk * 32;
#pragma unroll
                for (int nf = 0; nf < 7; nf++) {
                    uint32_t bh[4];
                    ldsm4(bh, kb + nf * (16 * RS));
                    mma16816(acc[0][2 * nf],     ah0, bh[0], bh[1]);
                    mma16816(acc[1][2 * nf],     ah1, bh[0], bh[1]);
                    mma16816(acc[0][2 * nf + 1], ah0, bh[2], bh[3]);
                    mma16816(acc[1][2 * nf + 1], ah1, bh[2], bh[3]);
                }
            }
            __syncthreads();
        }

        // epilogue: atomicAdd partials; kslice 0 also adds bias (out zeroed in k_misc)
#pragma unroll
        for (int mf = 0; mf < 2; mf++) {
            int r0 = m0 + wm * 32 + mf * 16 + g;
            int r1 = r0 + 8;
#pragma unroll
            for (int nf = 0; nf < 14; nf++) {
                int col = wn * 112 + nf * 8 + tg * 2;
                if (col < DD) {
                    float b0 = 0.f, b1 = 0.f;
                    if (ks == 0) { b0 = bias[col]; b1 = bias[col + 1]; }
                    if (r0 < NN) {
                        atomicAdd(&out[(size_t)r0 * DD + col],     acc[mf][nf][0] + b0);
                        atomicAdd(&out[(size_t)r0 * DD + col + 1], acc[mf][nf][1] + b1);
                    }
                    if (r1 < NN) {
                        atomicAdd(&out[(size_t)r1 * DD + col],     acc[mf][nf][2] + b0);
                        atomicAdd(&out[(size_t)r1 * DD + col + 1], acc[mf][nf][3] + b1);
                    }
                }
            }
        }
    }
}

extern "C" void kernel_launch(void* const* d_in, const int* in_sizes, int n_in,
                              void* d_out, int out_size) {
    const float* x      = (const float*)d_in[0];
    const float* weight = (const float*)d_in[1];
    const float* coeff  = (const float*)d_in[2];
    const float* selfw  = (const float*)d_in[3];
    const float* bias   = (const float*)d_in[4];
    const int*   eidx   = (const int*)d_in[5];
    const int*   etype  = (const int*)d_in[6];
    float*       out    = (float*)d_out;

    static void* p_deg = nullptr;
    if (!p_deg) {
        cudaGetSymbolAddress(&p_deg, g_deg);
        cudaFuncSetAttribute(k_gemm, cudaFuncAttributeMaxDynamicSharedMemorySize, SMEM_G);
    }

    cudaMemsetAsync(p_deg, 0, NN * sizeof(int));
    k_count<<<(EE + 255) / 256, 256>>>(eidx);
    k_scan<<<1, 256>>>();
    k_misc<<<NB_FILL + NB_W + NB_O, 256>>>(eidx, etype, weight, selfw, out);
    k_agg<<<NN, AGG_T>>>(x, coeff);
    k_gemm<<<GRID_G, GT, SMEM_G>>>(bias, out);
}